// round 4
// baseline (speedup 1.0000x reference)
#include <cuda_runtime.h>

#define WIDTH 4096
#define DEPTH 32
typedef unsigned long long ull;

// theta table, stage-ordered, contiguous per (t,tid): 4 float4 = 8 (cos,sin)
// pairs. index in float2 units: (t*256 + tid)*8 + k
__device__ float4 g_theta4[32 * 256 * 4];

static __device__ __forceinline__ ull pack2(float lo, float hi) {
    ull r; asm("mov.b64 %0, {%1,%2};" : "=l"(r) : "f"(lo), "f"(hi)); return r;
}
static __device__ __forceinline__ void unpack2(ull v, float &lo, float &hi) {
    asm("mov.b64 {%0,%1}, %2;" : "=f"(lo), "=f"(hi) : "l"(v));
}
static __device__ __forceinline__ ull mul2(ull a, ull b) {
    ull r; asm("mul.rn.f32x2 %0, %1, %2;" : "=l"(r) : "l"(a), "l"(b)); return r;
}
static __device__ __forceinline__ ull fma2(ull a, ull b, ull c) {
    ull r; asm("fma.rn.f32x2 %0, %1, %2, %3;" : "=l"(r) : "l"(a), "l"(b), "l"(c)); return r;
}

// logical column u from (pattern, register slot cr, thread id)
// pat 0: u[11:8]=cr                 pat 1: u[7:4]=cr   pat 2: u[3:0]=cr
static __device__ __forceinline__ int asmU_rt(int pat, int cr, int tid) {
    if (pat == 0) return (cr << 8) | tid;
    if (pat == 1) return (cr << 4) | (tid & 15) | ((tid & 0xF0) << 4);
    return cr | ((tid & 15) << 4) | ((tid & 0xF0) << 4);
}
template<int PAT> static __device__ __forceinline__ int asmU(int cr, int tid) {
    return asmU_rt(PAT, cr, tid);
}
// swizzle over 8B smem words: low nibble becomes tid[3:0]^tid[7:4]^cr in all
// patterns -> distinct within each half-warp -> conflict-free LDS/STS.64
static __device__ __forceinline__ int swz(int u) {
    return u ^ (((u >> 4) ^ (u >> 8)) & 15);
}

__global__ void bfly_theta_kernel(const float* __restrict__ params) {
    int idx = blockIdx.x * blockDim.x + threadIdx.x;   // 65536
    int t = idx >> 11;
    int tid = (idx >> 3) & 255;
    int k = idx & 7;
    int pat = (t >> 2) % 3;
    int m = 3 - (t & 3);                               // cr bit for this stage
    int i0 = ((k >> m) << (m + 1)) | (k & ((1 << m) - 1)); // pair slot, bit m=0
    int u = asmU_rt(pat, i0, tid);
    int s = t % 12;
    int ur = s ? (((u << s) | (u >> (12 - s))) & 4095) : u;  // rotl12(u,t)
    float th = params[(ur & 2047) * DEPTH + t];
    float c, sn;
    sincosf(th, &sn, &c);
    ((float2*)g_theta4)[idx] = make_float2(c, sn);     // idx = (t*256+tid)*8+k
}

template<int M>
static __device__ __forceinline__ void stage(ull d[16], int t, int tid) {
    const float4* th = g_theta4 + ((t << 8) + tid) * 4;
#pragma unroll
    for (int j = 0; j < 4; j++) {
        float4 q = __ldg(th + j);   // k=2j: (q.x,q.y)  k=2j+1: (q.z,q.w)
#pragma unroll
        for (int h = 0; h < 2; h++) {
            int k = 2 * j + h;
            float c = h ? q.z : q.x;
            float s = h ? q.w : q.y;
            ull cc = pack2(c, c);
            ull ss = pack2(s, s);
            ull ns = ss ^ 0x8000000080000000ULL;       // (-s,-s)
            int i0 = ((k >> M) << (M + 1)) | (k & ((1 << M) - 1));
            int i1 = i0 | (1 << M);
            ull x0 = d[i0], x1 = d[i1];
            d[i0] = fma2(x0, cc, mul2(x1, ss));        // y0 =  c*x0 + s*x1
            d[i1] = fma2(x0, ns, mul2(x1, cc));        // y1 = -s*x0 + c*x1
        }
    }
}

static __device__ __forceinline__ void phase4(ull d[16], int t0, int tid) {
    stage<3>(d, t0, tid);
    stage<2>(d, t0 + 1, tid);
    stage<1>(d, t0 + 2, tid);
    stage<0>(d, t0 + 3, tid);
}

template<int PO, int PN>
static __device__ __forceinline__ void xpose(ull d[16], int tid, ull* sm) {
#pragma unroll
    for (int cr = 0; cr < 16; cr++)
        sm[swz(asmU<PO>(cr, tid))] = d[cr];
    __syncthreads();
#pragma unroll
    for (int cr = 0; cr < 16; cr++)
        d[cr] = sm[swz(asmU<PN>(cr, tid))];
    __syncthreads();
}

__global__ __launch_bounds__(256, 4)
void bfly_main_kernel(const float* __restrict__ X, float* __restrict__ out) {
    __shared__ ull sm[4096];          // 32KB
    int tid = threadIdx.x;
    size_t row0 = (size_t)blockIdx.x * 2;
    const float* x = X + row0 * WIDTH;
    float* o = out + row0 * WIDTH;

    ull d[16];                        // d[cr] = rows (0,1) packed for column u
#pragma unroll
    for (int cr = 0; cr < 16; cr++) { // pattern-0 load, coalesced
        int u = (cr << 8) | tid;
        d[cr] = pack2(x[u], x[WIDTH + u]);
    }

    phase4(d, 0, tid);  xpose<0, 1>(d, tid, sm);
    phase4(d, 4, tid);  xpose<1, 2>(d, tid, sm);
    phase4(d, 8, tid);  xpose<2, 0>(d, tid, sm);
    phase4(d, 12, tid); xpose<0, 1>(d, tid, sm);
    phase4(d, 16, tid); xpose<1, 2>(d, tid, sm);
    phase4(d, 20, tid); xpose<2, 0>(d, tid, sm);
    phase4(d, 24, tid); xpose<0, 1>(d, tid, sm);
    phase4(d, 28, tid);

    // park in pattern 1 by logical u, then read so rotated output index
    // oc = rotl12(u,8) is coalesced: for oc=(cr<<8)|tid, u = rotl12(oc,4).
#pragma unroll
    for (int cr = 0; cr < 16; cr++)
        sm[swz(asmU<1>(cr, tid))] = d[cr];
    __syncthreads();
#pragma unroll
    for (int cr = 0; cr < 16; cr++) {
        int oc = (cr << 8) | tid;                 // output column
        int u = ((oc << 4) | (oc >> 8)) & 4095;   // rotl12(oc,4)
        ull v = sm[swz(u)];
        float a, b;
        unpack2(v, a, b);
        o[oc] = a;
        o[WIDTH + oc] = b;
    }
}

extern "C" void kernel_launch(void* const* d_in, const int* in_sizes, int n_in,
                              void* d_out, int out_size) {
    const float* X = (const float*)d_in[0];
    const float* params = (const float*)d_in[1];
    if (n_in >= 2 && in_sizes[0] == 2048 * 32) {  // guard against input-order swap
        X = (const float*)d_in[1];
        params = (const float*)d_in[0];
    }
    bfly_theta_kernel<<<256, 256>>>(params);
    bfly_main_kernel<<<8192, 256>>>(X, (float*)d_out);
}

// round 5
// speedup vs baseline: 2.4791x; 2.4791x over previous
#include <cuda_runtime.h>

#define WIDTH 4096
#define DEPTH 32
typedef unsigned long long ull;

// theta table: g_theta4[(t*4+j)*256 + tid] = (cos,sin,cos,sin) for k=2j, 2j+1
// -> lane-dense LDG.128 (consecutive tid = consecutive float4)
__device__ float4 g_theta4[32 * 4 * 256];

static __device__ __forceinline__ ull pack2(float lo, float hi) {
    ull r; asm("mov.b64 %0, {%1,%2};" : "=l"(r) : "f"(lo), "f"(hi)); return r;
}
static __device__ __forceinline__ void unpack2(ull v, float &lo, float &hi) {
    asm("mov.b64 {%0,%1}, %2;" : "=f"(lo), "=f"(hi) : "l"(v));
}
static __device__ __forceinline__ ull mul2(ull a, ull b) {
    ull r; asm("mul.rn.f32x2 %0, %1, %2;" : "=l"(r) : "l"(a), "l"(b)); return r;
}
static __device__ __forceinline__ ull fma2(ull a, ull b, ull c) {
    ull r; asm("fma.rn.f32x2 %0, %1, %2, %3;" : "=l"(r) : "l"(a), "l"(b), "l"(c)); return r;
}

// logical column u from (pattern, register slot cr, thread id)
// pat 0: u[11:8]=cr   pat 1: u[7:4]=cr   pat 2: u[3:0]=cr
static __device__ __forceinline__ int asmU_rt(int pat, int cr, int tid) {
    if (pat == 0) return (cr << 8) | tid;
    if (pat == 1) return (cr << 4) | (tid & 15) | ((tid & 0xF0) << 4);
    return cr | ((tid & 15) << 4) | ((tid & 0xF0) << 4);
}
template<int PAT> static __device__ __forceinline__ int asmU(int cr, int tid) {
    return asmU_rt(PAT, cr, tid);
}
// swizzle over 16B smem words; bank-slot bits stay injective in all patterns
static __device__ __forceinline__ int swz(int u) {
    return u ^ (((u >> 4) ^ (u >> 8)) & 15);
}

__global__ void bfly_theta_kernel(const float* __restrict__ params) {
    int idx = blockIdx.x * blockDim.x + threadIdx.x;   // 65536 float2 slots
    int t   = idx >> 11;
    int j   = (idx >> 9) & 3;
    int tid = (idx >> 1) & 255;
    int h   = idx & 1;
    int k   = 2 * j + h;
    int pat = (t >> 2) % 3;
    int m   = 3 - (t & 3);                                   // reg bit for stage
    int i0  = ((k >> m) << (m + 1)) | (k & ((1 << m) - 1));  // pair slot, bit m=0
    int u   = asmU_rt(pat, i0, tid);
    int s   = t % 12;
    int ur  = s ? (((u << s) | (u >> (12 - s))) & 4095) : u; // rotl12(u,t)
    float th = params[(ur & 2047) * DEPTH + t];
    float c, sn;
    sincosf(th, &sn, &c);
    ((float2*)g_theta4)[idx] = make_float2(c, sn);   // idx = 2*((t*4+j)*256+tid)+h
}

template<int M>
static __device__ __forceinline__ void stage(ull d[32], int t, int tid) {
    const float4* th = g_theta4 + (t << 10) + tid;
    float4 q[4];
#pragma unroll
    for (int j = 0; j < 4; j++) q[j] = __ldg(th + (j << 8));   // 4 dense LDG.128
#pragma unroll
    for (int j = 0; j < 4; j++) {
#pragma unroll
        for (int h = 0; h < 2; h++) {
            int k = 2 * j + h;
            float c = h ? q[j].z : q[j].x;
            float s = h ? q[j].w : q[j].y;
            ull cc = pack2(c, c);
            ull ss = pack2(s, s);
            ull ns = ss ^ 0x8000000080000000ULL;   // (-s,-s)
            int i0 = ((k >> M) << (M + 1)) | (k & ((1 << M) - 1));
            int i1 = i0 | (1 << M);
#pragma unroll
            for (int rp = 0; rp < 2; rp++) {
                ull x0 = d[2 * i0 + rp], x1 = d[2 * i1 + rp];
                d[2 * i0 + rp] = fma2(x0, cc, mul2(x1, ss));   // y0 =  c*x0 + s*x1
                d[2 * i1 + rp] = fma2(x0, ns, mul2(x1, cc));   // y1 = -s*x0 + c*x1
            }
        }
    }
}

static __device__ __forceinline__ void phase4(ull d[32], int t0, int tid) {
    stage<3>(d, t0, tid);
    stage<2>(d, t0 + 1, tid);
    stage<1>(d, t0 + 2, tid);
    stage<0>(d, t0 + 3, tid);
}

template<int PO, int PN>
static __device__ __forceinline__ void xpose(ull d[32], int tid, longlong2* sm) {
#pragma unroll
    for (int cr = 0; cr < 16; cr++)
        sm[swz(asmU<PO>(cr, tid))] =
            make_longlong2((long long)d[2 * cr], (long long)d[2 * cr + 1]);
    __syncthreads();
#pragma unroll
    for (int cr = 0; cr < 16; cr++) {
        longlong2 v = sm[swz(asmU<PN>(cr, tid))];
        d[2 * cr] = (ull)v.x;
        d[2 * cr + 1] = (ull)v.y;
    }
    __syncthreads();
}

// row r (0..3) of column-register cr
static __device__ __forceinline__ float getv(const ull d[32], int cr, int r) {
    float lo, hi;
    unpack2(d[2 * cr + (r >> 1)], lo, hi);
    return (r & 1) ? hi : lo;
}

__global__ __launch_bounds__(256, 2)
void bfly_main_kernel(const float* __restrict__ X, float* __restrict__ out) {
    extern __shared__ longlong2 sm[];   // 4096 x 16B = 64KB
    int tid = threadIdx.x;
    size_t row0 = (size_t)blockIdx.x * 4;
    const float* x = X + row0 * WIDTH;
    float* o = out + row0 * WIDTH;

    ull d[32];  // [cr*2+rp]: rp0 = rows(0,1) packed, rp1 = rows(2,3) packed
#pragma unroll
    for (int cr = 0; cr < 16; cr++) {   // pattern-0 load, lane-dense
        int u = (cr << 8) | tid;
        d[2 * cr]     = pack2(x[u],             x[WIDTH + u]);
        d[2 * cr + 1] = pack2(x[2 * WIDTH + u], x[3 * WIDTH + u]);
    }

    phase4(d, 0, tid);  xpose<0, 1>(d, tid, sm);
    phase4(d, 4, tid);  xpose<1, 2>(d, tid, sm);
    phase4(d, 8, tid);  xpose<2, 0>(d, tid, sm);
    phase4(d, 12, tid); xpose<0, 1>(d, tid, sm);
    phase4(d, 16, tid); xpose<1, 2>(d, tid, sm);
    phase4(d, 20, tid); xpose<2, 0>(d, tid, sm);
    phase4(d, 24, tid); xpose<0, 1>(d, tid, sm);
    phase4(d, 28, tid);

    // regs in pattern 1 over u; output col o = rotl12(u,8)
    //   = (tid[3:0]<<8) | (tid[7:4]<<4) | cr  -> 16 CONSECUTIVE cols per thread.
    // Direct store: 4 rows x 4 STG.128, no smem round, no barrier.
    int obase = ((tid & 15) << 8) | ((tid >> 4) << 4);
#pragma unroll
    for (int r = 0; r < 4; r++) {
        float4* op = (float4*)(o + (size_t)r * WIDTH + obase);
#pragma unroll
        for (int j = 0; j < 4; j++) {
            float4 w;
            w.x = getv(d, 4 * j + 0, r);
            w.y = getv(d, 4 * j + 1, r);
            w.z = getv(d, 4 * j + 2, r);
            w.w = getv(d, 4 * j + 3, r);
            op[j] = w;
        }
    }
}

extern "C" void kernel_launch(void* const* d_in, const int* in_sizes, int n_in,
                              void* d_out, int out_size) {
    const float* X = (const float*)d_in[0];
    const float* params = (const float*)d_in[1];
    if (n_in >= 2 && in_sizes[0] == 2048 * 32) {  // guard against input-order swap
        X = (const float*)d_in[1];
        params = (const float*)d_in[0];
    }
    cudaFuncSetAttribute(bfly_main_kernel,
                         cudaFuncAttributeMaxDynamicSharedMemorySize, 65536);
    bfly_theta_kernel<<<256, 256>>>(params);
    bfly_main_kernel<<<4096, 256, 65536>>>(X, (float*)d_out);
}

// round 6
// speedup vs baseline: 2.5206x; 1.0167x over previous
#include <cuda_runtime.h>

#define WIDTH 4096
#define DEPTH 32
typedef unsigned long long ull;

// theta table: g_theta4[(t*4+j)*256 + tid] = (cos,sin,cos,sin) for k=2j, 2j+1
// lane-dense: consecutive tid = consecutive float4 -> dense LDG.128
__device__ float4 g_theta4[32 * 4 * 256];

static __device__ __forceinline__ ull pack2(float lo, float hi) {
    ull r; asm("mov.b64 %0, {%1,%2};" : "=l"(r) : "f"(lo), "f"(hi)); return r;
}
static __device__ __forceinline__ void unpack2(ull v, float &lo, float &hi) {
    asm("mov.b64 {%0,%1}, %2;" : "=f"(lo), "=f"(hi) : "l"(v));
}
static __device__ __forceinline__ ull mul2(ull a, ull b) {
    ull r; asm("mul.rn.f32x2 %0, %1, %2;" : "=l"(r) : "l"(a), "l"(b)); return r;
}
static __device__ __forceinline__ ull fma2(ull a, ull b, ull c) {
    ull r; asm("fma.rn.f32x2 %0, %1, %2, %3;" : "=l"(r) : "l"(a), "l"(b), "l"(c)); return r;
}

// logical column u from (pattern, register slot cr, thread id)
// pat 0: u[11:8]=cr   pat 1: u[7:4]=cr   pat 2: u[3:0]=cr
static __device__ __forceinline__ int asmU_rt(int pat, int cr, int tid) {
    if (pat == 0) return (cr << 8) | tid;
    if (pat == 1) return (cr << 4) | (tid & 15) | ((tid & 0xF0) << 4);
    return cr | ((tid & 15) << 4) | ((tid & 0xF0) << 4);
}
template<int PAT> static __device__ __forceinline__ int asmU(int cr, int tid) {
    return asmU_rt(PAT, cr, tid);
}
// swizzle over 16B smem words; bank-slot bits stay injective in all patterns
static __device__ __forceinline__ int swz(int u) {
    return u ^ (((u >> 4) ^ (u >> 8)) & 15);
}

__global__ void bfly_theta_kernel(const float* __restrict__ params) {
    int idx = blockIdx.x * blockDim.x + threadIdx.x;   // 65536 float2 slots
    int t   = idx >> 11;
    int j   = (idx >> 9) & 3;
    int tid = (idx >> 1) & 255;
    int h   = idx & 1;
    int k   = 2 * j + h;
    int pat = (t >> 2) % 3;
    int m   = 3 - (t & 3);                                   // reg bit for stage
    int i0  = ((k >> m) << (m + 1)) | (k & ((1 << m) - 1));  // pair slot, bit m=0
    int u   = asmU_rt(pat, i0, tid);
    int s   = t % 12;
    int ur  = s ? (((u << s) | (u >> (12 - s))) & 4095) : u; // rotl12(u,t)
    float th = params[(ur & 2047) * DEPTH + t];
    float c, sn;
    sincosf(th, &sn, &c);
    ((float2*)g_theta4)[idx] = make_float2(c, sn);   // idx = 2*((t*4+j)*256+tid)+h
}

static __device__ __forceinline__ void stage_load(float4 q[4], int t, int tid) {
    const float4* th = g_theta4 + (t << 10) + tid;
#pragma unroll
    for (int j = 0; j < 4; j++) q[j] = __ldg(th + (j << 8));
}

template<int M>
static __device__ __forceinline__ void stage_compute(ull d[32], const float4 q[4]) {
#pragma unroll
    for (int j = 0; j < 4; j++) {
#pragma unroll
        for (int h = 0; h < 2; h++) {
            int k = 2 * j + h;
            float c = h ? q[j].z : q[j].x;
            float s = h ? q[j].w : q[j].y;
            ull cc = pack2(c, c);
            ull ss = pack2(s, s);
            ull ns = ss ^ 0x8000000080000000ULL;   // (-s,-s)
            int i0 = ((k >> M) << (M + 1)) | (k & ((1 << M) - 1));
            int i1 = i0 | (1 << M);
#pragma unroll
            for (int rp = 0; rp < 2; rp++) {
                ull x0 = d[2 * i0 + rp], x1 = d[2 * i1 + rp];
                d[2 * i0 + rp] = fma2(x0, cc, mul2(x1, ss));   // y0 =  c*x0 + s*x1
                d[2 * i1 + rp] = fma2(x0, ns, mul2(x1, cc));   // y1 = -s*x0 + c*x1
            }
        }
    }
}

template<int PO, int PN>
static __device__ __forceinline__ void xpose(ull d[32], int tid, longlong2* sm) {
#pragma unroll
    for (int cr = 0; cr < 16; cr++)
        sm[swz(asmU<PO>(cr, tid))] =
            make_longlong2((long long)d[2 * cr], (long long)d[2 * cr + 1]);
    __syncthreads();
#pragma unroll
    for (int cr = 0; cr < 16; cr++) {
        longlong2 v = sm[swz(asmU<PN>(cr, tid))];
        d[2 * cr] = (ull)v.x;
        d[2 * cr + 1] = (ull)v.y;
    }
    __syncthreads();
}

// row r (0..3) of column-register cr
static __device__ __forceinline__ float getv(const ull d[32], int cr, int r) {
    float lo, hi;
    unpack2(d[2 * cr + (r >> 1)], lo, hi);
    return (r & 1) ? hi : lo;
}

// prefetch stage t+1 theta into B, then run stage t from A
#define STEP(t, A, B)                       \
    stage_load(B, (t) + 1, tid);            \
    stage_compute<3 - ((t) & 3)>(d, A);

__global__ __launch_bounds__(256, 2)
void bfly_main_kernel(const float* __restrict__ X, float* __restrict__ out) {
    extern __shared__ longlong2 sm[];   // 4096 x 16B = 64KB
    int tid = threadIdx.x;
    size_t row0 = (size_t)blockIdx.x * 4;
    const float* x = X + row0 * WIDTH;
    float* o = out + row0 * WIDTH;

    float4 qa[4], qb[4];
    stage_load(qa, 0, tid);             // prefetch stage 0 behind input loads

    ull d[32];  // [cr*2+rp]: rp0 = rows(0,1) packed, rp1 = rows(2,3) packed
#pragma unroll
    for (int cr = 0; cr < 16; cr++) {   // pattern-0 load, lane-dense
        int u = (cr << 8) | tid;
        d[2 * cr]     = pack2(x[u],             x[WIDTH + u]);
        d[2 * cr + 1] = pack2(x[2 * WIDTH + u], x[3 * WIDTH + u]);
    }

    STEP(0, qa, qb)  STEP(1, qb, qa)  STEP(2, qa, qb)  STEP(3, qb, qa)
    xpose<0, 1>(d, tid, sm);
    STEP(4, qa, qb)  STEP(5, qb, qa)  STEP(6, qa, qb)  STEP(7, qb, qa)
    xpose<1, 2>(d, tid, sm);
    STEP(8, qa, qb)  STEP(9, qb, qa)  STEP(10, qa, qb) STEP(11, qb, qa)
    xpose<2, 0>(d, tid, sm);
    STEP(12, qa, qb) STEP(13, qb, qa) STEP(14, qa, qb) STEP(15, qb, qa)
    xpose<0, 1>(d, tid, sm);
    STEP(16, qa, qb) STEP(17, qb, qa) STEP(18, qa, qb) STEP(19, qb, qa)
    xpose<1, 2>(d, tid, sm);
    STEP(20, qa, qb) STEP(21, qb, qa) STEP(22, qa, qb) STEP(23, qb, qa)
    xpose<2, 0>(d, tid, sm);
    STEP(24, qa, qb) STEP(25, qb, qa) STEP(26, qa, qb) STEP(27, qb, qa)
    xpose<0, 1>(d, tid, sm);
    STEP(28, qa, qb) STEP(29, qb, qa) STEP(30, qa, qb)
    stage_compute<0>(d, qb);            // stage 31, no prefetch

    // regs in pattern 1 over u; output col o = rotl12(u,8)
    //   = (tid[3:0]<<8) | (tid[7:4]<<4) | cr  -> 16 CONSECUTIVE cols per thread.
    int obase = ((tid & 15) << 8) | ((tid >> 4) << 4);
#pragma unroll
    for (int r = 0; r < 4; r++) {
        float4* op = (float4*)(o + (size_t)r * WIDTH + obase);
#pragma unroll
        for (int j = 0; j < 4; j++) {
            float4 w;
            w.x = getv(d, 4 * j + 0, r);
            w.y = getv(d, 4 * j + 1, r);
            w.z = getv(d, 4 * j + 2, r);
            w.w = getv(d, 4 * j + 3, r);
            op[j] = w;
        }
    }
}

extern "C" void kernel_launch(void* const* d_in, const int* in_sizes, int n_in,
                              void* d_out, int out_size) {
    const float* X = (const float*)d_in[0];
    const float* params = (const float*)d_in[1];
    if (n_in >= 2 && in_sizes[0] == 2048 * 32) {  // guard against input-order swap
        X = (const float*)d_in[1];
        params = (const float*)d_in[0];
    }
    cudaFuncSetAttribute(bfly_main_kernel,
                         cudaFuncAttributeMaxDynamicSharedMemorySize, 65536);
    bfly_theta_kernel<<<256, 256>>>(params);
    bfly_main_kernel<<<4096, 256, 65536>>>(X, (float*)d_out);
}